// round 7
// baseline (speedup 1.0000x reference)
#include <cuda_runtime.h>
#include <cstdint>

// HungarianMatcher cost matrix:
//   C[b,q,t] = 5*L1(pred_box[b,q], tgt_box[t])
//            + 2*focal_class_cost(sigmoid(logit[b,q,tgt_id[t]]))
//            - 2*GIoU(xyxy(pred_box), xyxy(tgt_box))
// Shapes: logits [14400,91], pred_boxes [14400,4], tgt_boxes [1600,4], tgt_ids [1600]
// Output [14400,1600] f32 (92 MB) -> HBM-write floor ~15us; compute ~27 fma ops/pair.

#define QT      8      // queries per block (one per warp)
#define THREADS 256
#define NT_MAX  2048   // max targets supported (actual nt=1600)

__global__ __launch_bounds__(THREADS)
void matcher_cost_kernel(
    const float* __restrict__ logits,   // [nqtot, nc]
    const float* __restrict__ pboxes,   // [nqtot, 4] cxcywh
    const float* __restrict__ tboxes,   // [nt, 4]    cxcywh
    const void*  __restrict__ tids_raw, // [nt] int32 or int64 (detected)
    float* __restrict__ out,            // [nqtot, nt]
    int nt, int nc, int nqtot)
{
    // Interleaved target storage: s_tb[t&3][t>>2] so that a thread reading 4
    // consecutive targets does 4 conflict-free LDS.128 (lane stride = 16B).
    __shared__ float4 s_tb[4][NT_MAX / 4];
    __shared__ int    s_id[4][NT_MAX / 4];
    __shared__ float  s_cc[QT][96];      // focal class cost table (padded)
    __shared__ float4 s_qc[QT];          // query cxcywh
    __shared__ float4 s_qx[QT];          // query xyxy
    __shared__ float  s_qa[QT];          // query area
    __shared__ int    s_is64;

    const int tid   = threadIdx.x;
    const int qbase = blockIdx.x * QT;

    // ---- dtype detection for tgt_ids (int64 vs int32) -------------------
    // Read first nt/2 longs (== nt*4 bytes: safe under either layout).
    // int64 storage => every 8-byte value is a valid id in [0, nc).
    // int32 storage => high words are random ids, almost surely >= nc as i64.
    if (tid == 0) s_is64 = 1;
    __syncthreads();
    const long long* idl = (const long long*)tids_raw;
    for (int i = tid; i < (nt >> 1); i += THREADS) {
        long long v = idl[i];
        if (v < 0 || v >= (long long)nc) s_is64 = 0;   // benign race: all write 0
    }
    __syncthreads();
    const bool is64 = (s_is64 != 0);

    // ---- stage targets into SMEM (once per block, amortized over QT rows)
    for (int t = tid; t < nt; t += THREADS) {
        float4 b = ((const float4*)tboxes)[t];
        s_tb[t & 3][t >> 2] = b;
        int id = is64 ? (int)idl[t] : ((const int*)tids_raw)[t];
        s_id[t & 3][t >> 2] = id;
    }

    // ---- focal class-cost table: depends only on (query, class) ----------
    // pos = ALPHA*(1-p)^2 * -log(p+eps); neg = (1-ALPHA)*p^2 * -log(1-p+eps)
    for (int i = tid; i < QT * nc; i += THREADS) {
        int ql = i / nc;
        int c  = i - ql * nc;
        int q  = qbase + ql;
        float cc = 0.0f;
        if (q < nqtot) {
            float x = logits[(size_t)q * nc + c];
            float p = __fdividef(1.0f, 1.0f + __expf(-x));
            float pos = 0.25f * (1.0f - p) * (1.0f - p) * (-__logf(p + 1e-8f));
            float neg = 0.75f * p * p * (-__logf(1.0f - p + 1e-8f));
            cc = pos - neg;
        }
        s_cc[ql][c] = cc;
    }

    // ---- per-query precompute (cxcywh, xyxy, area) ------------------------
    if (tid < QT) {
        int q = qbase + tid;
        float4 b = (q < nqtot) ? ((const float4*)pboxes)[q]
                               : make_float4(0.25f, 0.25f, 0.5f, 0.5f);
        s_qc[tid] = b;
        float4 x;
        x.x = fmaf(-0.5f, b.z, b.x);  // x0
        x.y = fmaf(-0.5f, b.w, b.y);  // y0
        x.z = fmaf( 0.5f, b.z, b.x);  // x1
        x.w = fmaf( 0.5f, b.w, b.y);  // y1
        s_qx[tid] = x;
        s_qa[tid] = b.z * b.w;
    }
    __syncthreads();

    // ---- main pairwise loop: warp w owns query row qbase+w ----------------
    const int w    = tid >> 5;
    const int lane = tid & 31;
    const int q    = qbase + w;
    if (q >= nqtot) return;

    const float4 qc = s_qc[w];
    const float4 qx = s_qx[w];
    const float  qa = s_qa[w];
    const float* ctab = s_cc[w];

    float4* __restrict__ orow = (float4*)(out + (size_t)q * nt);
    const int ncol = nt >> 2;

    for (int c = lane; c < ncol; c += 32) {
        float4 r;
#pragma unroll
        for (int j = 0; j < 4; j++) {
            float4 tb = s_tb[j][c];                    // conflict-free LDS.128
            // tgt cxcywh -> xyxy + area (5 fma-pipe ops)
            float tx0 = fmaf(-0.5f, tb.z, tb.x);
            float ty0 = fmaf(-0.5f, tb.w, tb.y);
            float tx1 = fmaf( 0.5f, tb.z, tb.x);
            float ty1 = fmaf( 0.5f, tb.w, tb.y);
            float ta  = tb.z * tb.w;
            // L1 on cxcywh (8 ops; |x| folded into FADD operand modifiers)
            float l1 = fabsf(qc.x - tb.x) + fabsf(qc.y - tb.y)
                     + fabsf(qc.z - tb.z) + fabsf(qc.w - tb.w);
            // intersection / union
            float ix0 = fmaxf(qx.x, tx0), iy0 = fmaxf(qx.y, ty0);
            float ix1 = fminf(qx.z, tx1), iy1 = fminf(qx.w, ty1);
            float iw  = fmaxf(ix1 - ix0, 0.0f);
            float ih  = fmaxf(iy1 - iy0, 0.0f);
            float inter = iw * ih;
            float uni   = (qa + ta) - inter;
            // enclosing box (mins/maxes -> always non-negative extents)
            float ex0 = fminf(qx.x, tx0), ey0 = fminf(qx.y, ty0);
            float ex1 = fmaxf(qx.z, tx1), ey1 = fmaxf(qx.w, ty1);
            float ea  = (ex1 - ex0) * (ey1 - ey0);
            // giou = iou - (ea - uni)/ea = inter/uni + uni/ea - 1
            float giou = fmaf(inter, __frcp_rn(uni) * 1.0f,
                              uni * __frcp_rn(ea)) - 1.0f;
            // class cost lookup (91-entry table, random banks, avg ~2-way)
            float cc = ctab[s_id[j][c]];
            // C = 5*L1 + 2*cc - 2*giou
            float cost = fmaf(5.0f, l1, fmaf(2.0f, cc, -2.0f * giou));
            ((float*)&r)[j] = cost;
        }
        orow[c] = r;                                   // coalesced STG.128
    }
}

extern "C" void kernel_launch(void* const* d_in, const int* in_sizes, int n_in,
                              void* d_out, int out_size) {
    const float* logits = (const float*)d_in[0];   // [bs*nq, nc]
    const float* pboxes = (const float*)d_in[1];   // [bs*nq, 4]
    const float* tboxes = (const float*)d_in[2];   // [nt, 4]
    const void*  tids   = d_in[3];                 // [nt] i32/i64

    const int nt    = in_sizes[3];                 // 1600
    const int nqtot = in_sizes[1] / 4;             // 14400
    const int nc    = in_sizes[0] / nqtot;         // 91

    float* out = (float*)d_out;

    const int grid = (nqtot + QT - 1) / QT;        // 1800 blocks
    matcher_cost_kernel<<<grid, THREADS>>>(logits, pboxes, tboxes, tids,
                                           out, nt, nc, nqtot);
}